// round 2
// baseline (speedup 1.0000x reference)
#include <cuda_runtime.h>
#include <math.h>

namespace {
constexpr int B = 8, S = 4096, E = 1024, H = 8, W = 128, D = 128;
constexpr int NWIN = S / W;          // 32
constexpr int TPAD = 132;            // padded row stride (floats) for transposed smem tiles
constexpr float SCALE = 0.08838834764831845f;  // D^-0.5
}

// Scratch (device globals — no runtime allocation allowed)
__device__ float g_q[(size_t)B * H * S * D];
__device__ float g_k[(size_t)B * H * S * D];
__device__ float g_v[(size_t)B * H * S * D];
__device__ float g_att[(size_t)B * S * E];

// ---------------------------------------------------------------------------
// Tile loaders: 128x128 fp32 tile, 256 threads.
// Coalesced float4 gmem reads (one warp = one 512B row), scatter into smem.
// ---------------------------------------------------------------------------

// Transposed: smT[col][row], row stride TPAD. Optional scale folded in.
__device__ __forceinline__ void load_tile_T(const float* __restrict__ g, int row_stride,
                                            float* __restrict__ smT, int t, float scale)
{
#pragma unroll
    for (int v = 0; v < 16; v++) {
        int lin = t + v * 256;          // quad index 0..4095
        int row = lin >> 5;             // 0..127
        int qc  = (lin & 31) << 2;      // column base 0..124
        float4 f = *reinterpret_cast<const float4*>(g + (long)row * row_stride + qc);
        smT[(qc + 0) * TPAD + row] = f.x * scale;
        smT[(qc + 1) * TPAD + row] = f.y * scale;
        smT[(qc + 2) * TPAD + row] = f.z * scale;
        smT[(qc + 3) * TPAD + row] = f.w * scale;
    }
}

// Natural: sm[row][col], row stride 128 (float4-aligned).
__device__ __forceinline__ void load_tile_N(const float* __restrict__ g, int row_stride,
                                            float* __restrict__ sm, int t)
{
#pragma unroll
    for (int v = 0; v < 16; v++) {
        int lin = t + v * 256;
        int row = lin >> 5;
        int qc  = (lin & 31) << 2;
        *reinterpret_cast<float4*>(sm + row * 128 + qc) =
            *reinterpret_cast<const float4*>(g + (long)row * row_stride + qc);
    }
}

// ---------------------------------------------------------------------------
// Kernel 1: per-head projection. out[b,h,s,o] = sum_d x[b,s,h*D+d] * Wt[o,d]
// grid (S/128, H, B), 256 threads, 8x8 register tile per thread.
// ---------------------------------------------------------------------------
__global__ void __launch_bounds__(256)
proj_kernel(const float* __restrict__ x, const float* __restrict__ Wt,
            float* __restrict__ out)
{
    extern __shared__ float sm[];
    float* xsT = sm;                 // [128][TPAD]  xsT[d][row]
    float* WsT = sm + 128 * TPAD;    // [128][TPAD]  WsT[d][o]

    const int t  = threadIdx.x;
    const int st = blockIdx.x, h = blockIdx.y, b = blockIdx.z;
    const int s0 = st * 128;

    load_tile_T(x + ((long)(b * S + s0)) * E + h * D, E, xsT, t, 1.0f);
    load_tile_T(Wt, D, WsT, t, 1.0f);
    __syncthreads();

    const int r0 = (t >> 4) << 3;
    const int c0 = (t & 15) << 3;
    float acc[8][8] = {};

#pragma unroll 4
    for (int kk = 0; kk < 128; kk++) {
        float4 a0 = *reinterpret_cast<float4*>(&xsT[kk * TPAD + r0]);
        float4 a1 = *reinterpret_cast<float4*>(&xsT[kk * TPAD + r0 + 4]);
        float4 b0 = *reinterpret_cast<float4*>(&WsT[kk * TPAD + c0]);
        float4 b1 = *reinterpret_cast<float4*>(&WsT[kk * TPAD + c0 + 4]);
        float a[8] = {a0.x, a0.y, a0.z, a0.w, a1.x, a1.y, a1.z, a1.w};
        float bb[8] = {b0.x, b0.y, b0.z, b0.w, b1.x, b1.y, b1.z, b1.w};
#pragma unroll
        for (int i = 0; i < 8; i++)
#pragma unroll
            for (int j = 0; j < 8; j++)
                acc[i][j] = fmaf(a[i], bb[j], acc[i][j]);
    }

    long ob = ((long)(b * H + h) * S + s0 + r0) * D + c0;
#pragma unroll
    for (int i = 0; i < 8; i++) {
        *reinterpret_cast<float4*>(&out[ob + (long)i * D]) =
            make_float4(acc[i][0], acc[i][1], acc[i][2], acc[i][3]);
        *reinterpret_cast<float4*>(&out[ob + (long)i * D + 4]) =
            make_float4(acc[i][4], acc[i][5], acc[i][6], acc[i][7]);
    }
}

// ---------------------------------------------------------------------------
// Kernel 2: sliding-window attention. One block per (window, head, batch).
// Flash-style over the 3 neighbor windows; skipped out-of-range window ==
// reference's finfo.min mask (exp underflows to exactly 0).
// Output layout [b, s, h*D+d] so fc_out reads contiguously.
// ---------------------------------------------------------------------------
__global__ void __launch_bounds__(256)
attn_kernel(const float* __restrict__ gq, const float* __restrict__ gk,
            const float* __restrict__ gv, float* __restrict__ gout)
{
    extern __shared__ float sm[];
    float* qsT = sm;                               // [128][TPAD]  q^T (pre-scaled)
    float* ksT = sm + 128 * TPAD;                  // [128][TPAD]  k^T, reused as p^T
    float* vs  = sm + 2 * 128 * TPAD;              // [128][128]   v natural

    const int t  = threadIdx.x;
    const int wi = blockIdx.x, h = blockIdx.y, b = blockIdx.z;
    const long base = (long)(b * H + h) * S * D;

    load_tile_T(gq + base + (long)wi * W * D, D, qsT, t, SCALE);

    const int r0 = (t >> 4) << 3;   // query rows owned
    const int c0 = (t & 15) << 3;   // key cols (phase 1) / d cols (phase 2)

    float m[8], l[8], acc[8][8] = {};
#pragma unroll
    for (int i = 0; i < 8; i++) { m[i] = -1e30f; l[i] = 0.0f; }

    for (int c = 0; c < 3; c++) {
        const int j = wi - 1 + c;
        if (j < 0 || j >= NWIN) continue;     // uniform across block

        __syncthreads();  // previous PV done reading ksT/vs; qsT load visible
        load_tile_T(gk + base + (long)j * W * D, D, ksT, t, 1.0f);
        load_tile_N(gv + base + (long)j * W * D, D, vs, t);
        __syncthreads();

        // --- S = q k^T (scaled) ---
        float s[8][8] = {};
#pragma unroll 4
        for (int kk = 0; kk < 128; kk++) {
            float4 a0 = *reinterpret_cast<float4*>(&qsT[kk * TPAD + r0]);
            float4 a1 = *reinterpret_cast<float4*>(&qsT[kk * TPAD + r0 + 4]);
            float4 b0 = *reinterpret_cast<float4*>(&ksT[kk * TPAD + c0]);
            float4 b1 = *reinterpret_cast<float4*>(&ksT[kk * TPAD + c0 + 4]);
            float a[8] = {a0.x, a0.y, a0.z, a0.w, a1.x, a1.y, a1.z, a1.w};
            float bb[8] = {b0.x, b0.y, b0.z, b0.w, b1.x, b1.y, b1.z, b1.w};
#pragma unroll
            for (int i = 0; i < 8; i++)
#pragma unroll
                for (int jj = 0; jj < 8; jj++)
                    s[i][jj] = fmaf(a[i], bb[jj], s[i][jj]);
        }

        // --- online softmax (row stats across the 16-lane tx group) ---
        float mn[8], alpha[8];
#pragma unroll
        for (int i = 0; i < 8; i++) {
            float cm = s[i][0];
#pragma unroll
            for (int jj = 1; jj < 8; jj++) cm = fmaxf(cm, s[i][jj]);
#pragma unroll
            for (int off = 8; off >= 1; off >>= 1)
                cm = fmaxf(cm, __shfl_xor_sync(0xffffffffu, cm, off));
            mn[i] = fmaxf(m[i], cm);
            alpha[i] = __expf(m[i] - mn[i]);
            float rs = 0.0f;
#pragma unroll
            for (int jj = 0; jj < 8; jj++) {
                s[i][jj] = __expf(s[i][jj] - mn[i]);
                rs += s[i][jj];
            }
#pragma unroll
            for (int off = 8; off >= 1; off >>= 1)
                rs += __shfl_xor_sync(0xffffffffu, rs, off);
            l[i] = l[i] * alpha[i] + rs;
            m[i] = mn[i];
        }
#pragma unroll
        for (int i = 0; i < 8; i++)
#pragma unroll
            for (int jj = 0; jj < 8; jj++) acc[i][jj] *= alpha[i];

        // --- write p^T into ksT (all reads of k finished) ---
        __syncthreads();
#pragma unroll
        for (int jj = 0; jj < 8; jj++) {
            *reinterpret_cast<float4*>(&ksT[(c0 + jj) * TPAD + r0]) =
                make_float4(s[0][jj], s[1][jj], s[2][jj], s[3][jj]);
            *reinterpret_cast<float4*>(&ksT[(c0 + jj) * TPAD + r0 + 4]) =
                make_float4(s[4][jj], s[5][jj], s[6][jj], s[7][jj]);
        }
        __syncthreads();

        // --- acc += p v ---
#pragma unroll 4
        for (int kk = 0; kk < 128; kk++) {
            float4 a0 = *reinterpret_cast<float4*>(&ksT[kk * TPAD + r0]);
            float4 a1 = *reinterpret_cast<float4*>(&ksT[kk * TPAD + r0 + 4]);
            float4 b0 = *reinterpret_cast<float4*>(&vs[kk * 128 + c0]);
            float4 b1 = *reinterpret_cast<float4*>(&vs[kk * 128 + c0 + 4]);
            float a[8] = {a0.x, a0.y, a0.z, a0.w, a1.x, a1.y, a1.z, a1.w};
            float bb[8] = {b0.x, b0.y, b0.z, b0.w, b1.x, b1.y, b1.z, b1.w};
#pragma unroll
            for (int i = 0; i < 8; i++)
#pragma unroll
                for (int jj = 0; jj < 8; jj++)
                    acc[i][jj] = fmaf(a[i], bb[jj], acc[i][jj]);
        }
    }

    // epilogue: normalize, store to [b, s, h*D + d]
#pragma unroll
    for (int i = 0; i < 8; i++) {
        float inv = 1.0f / l[i];
        long ob = ((long)(b * S + wi * W + r0 + i)) * E + h * D + c0;
        *reinterpret_cast<float4*>(&gout[ob]) =
            make_float4(acc[i][0] * inv, acc[i][1] * inv, acc[i][2] * inv, acc[i][3] * inv);
        *reinterpret_cast<float4*>(&gout[ob + 4]) =
            make_float4(acc[i][4] * inv, acc[i][5] * inv, acc[i][6] * inv, acc[i][7] * inv);
    }
}

// ---------------------------------------------------------------------------
// Kernel 3: fc_out. y[m,o] = sum_e att[m,e]*Wo[o,e] + bo[o]
// M = B*S = 32768, N = K = 1024. grid (N/128, M/128), 128x128 tile, KC=64.
// ---------------------------------------------------------------------------
__global__ void __launch_bounds__(256)
fc_kernel(const float* __restrict__ att, const float* __restrict__ Wo,
          const float* __restrict__ bo, float* __restrict__ y)
{
    extern __shared__ float sm[];
    float* aT = sm;               // [64][TPAD]  a^T chunk
    float* bT = sm + 64 * TPAD;   // [64][TPAD]  Wo^T chunk

    const int t  = threadIdx.x;
    const int n0 = blockIdx.x * 128;
    const int m0 = blockIdx.y * 128;
    const int r0 = (t >> 4) << 3;
    const int c0 = (t & 15) << 3;

    float acc[8][8] = {};

    for (int e0 = 0; e0 < E; e0 += 64) {
        __syncthreads();
#pragma unroll
        for (int v = 0; v < 8; v++) {
            int lin = t + v * 256;       // quad index 0..2047
            int row = lin >> 4;          // 0..127
            int qc  = (lin & 15) << 2;   // 0..60
            float4 f = *reinterpret_cast<const float4*>(att + (long)(m0 + row) * E + e0 + qc);
            aT[(qc + 0) * TPAD + row] = f.x;
            aT[(qc + 1) * TPAD + row] = f.y;
            aT[(qc + 2) * TPAD + row] = f.z;
            aT[(qc + 3) * TPAD + row] = f.w;
            float4 g = *reinterpret_cast<const float4*>(Wo + (long)(n0 + row) * E + e0 + qc);
            bT[(qc + 0) * TPAD + row] = g.x;
            bT[(qc + 1) * TPAD + row] = g.y;
            bT[(qc + 2) * TPAD + row] = g.z;
            bT[(qc + 3) * TPAD + row] = g.w;
        }
        __syncthreads();

#pragma unroll 4
        for (int kk = 0; kk < 64; kk++) {
            float4 a0 = *reinterpret_cast<float4*>(&aT[kk * TPAD + r0]);
            float4 a1 = *reinterpret_cast<float4*>(&aT[kk * TPAD + r0 + 4]);
            float4 b0 = *reinterpret_cast<float4*>(&bT[kk * TPAD + c0]);
            float4 b1 = *reinterpret_cast<float4*>(&bT[kk * TPAD + c0 + 4]);
            float a[8] = {a0.x, a0.y, a0.z, a0.w, a1.x, a1.y, a1.z, a1.w};
            float bb[8] = {b0.x, b0.y, b0.z, b0.w, b1.x, b1.y, b1.z, b1.w};
#pragma unroll
            for (int i = 0; i < 8; i++)
#pragma unroll
                for (int jj = 0; jj < 8; jj++)
                    acc[i][jj] = fmaf(a[i], bb[jj], acc[i][jj]);
        }
    }

    float bias[8];
#pragma unroll
    for (int jj = 0; jj < 8; jj++) bias[jj] = bo[n0 + c0 + jj];

#pragma unroll
    for (int i = 0; i < 8; i++) {
        long ob = (long)(m0 + r0 + i) * E + n0 + c0;
        *reinterpret_cast<float4*>(&y[ob]) =
            make_float4(acc[i][0] + bias[0], acc[i][1] + bias[1],
                        acc[i][2] + bias[2], acc[i][3] + bias[3]);
        *reinterpret_cast<float4*>(&y[ob + 4]) =
            make_float4(acc[i][4] + bias[4], acc[i][5] + bias[5],
                        acc[i][6] + bias[6], acc[i][7] + bias[7]);
    }
}

// ---------------------------------------------------------------------------
// Launcher
// ---------------------------------------------------------------------------
extern "C" void kernel_launch(void* const* d_in, const int* in_sizes, int n_in,
                              void* d_out, int out_size)
{
    const float* values = (const float*)d_in[0];
    const float* keys   = (const float*)d_in[1];
    const float* query  = (const float*)d_in[2];
    const float* Wv     = (const float*)d_in[3];
    const float* Wk     = (const float*)d_in[4];
    const float* Wq     = (const float*)d_in[5];
    const float* Wo     = (const float*)d_in[6];
    const float* bo     = (const float*)d_in[7];
    float* out = (float*)d_out;

    float *q, *k, *v, *att;
    cudaGetSymbolAddress((void**)&q, g_q);
    cudaGetSymbolAddress((void**)&k, g_k);
    cudaGetSymbolAddress((void**)&v, g_v);
    cudaGetSymbolAddress((void**)&att, g_att);

    const size_t proj_smem = (size_t)2 * 128 * TPAD * sizeof(float);              // 135168
    const size_t attn_smem = ((size_t)2 * 128 * TPAD + 128 * 128) * sizeof(float); // 200704
    const size_t fc_smem   = (size_t)2 * 64 * TPAD * sizeof(float);               // 67584

    cudaFuncSetAttribute(proj_kernel, cudaFuncAttributeMaxDynamicSharedMemorySize, (int)proj_smem);
    cudaFuncSetAttribute(attn_kernel, cudaFuncAttributeMaxDynamicSharedMemorySize, (int)attn_smem);
    cudaFuncSetAttribute(fc_kernel,   cudaFuncAttributeMaxDynamicSharedMemorySize, (int)fc_smem);

    dim3 pg(S / 128, H, B);
    proj_kernel<<<pg, 256, proj_smem>>>(query,  Wq, q);
    proj_kernel<<<pg, 256, proj_smem>>>(keys,   Wk, k);
    proj_kernel<<<pg, 256, proj_smem>>>(values, Wv, v);

    attn_kernel<<<dim3(NWIN, H, B), 256, attn_smem>>>(q, k, v, att);

    fc_kernel<<<dim3(E / 128, (B * S) / 128), 256, fc_smem>>>(att, Wo, bo, out);
}

// round 3
// speedup vs baseline: 1.0024x; 1.0024x over previous
#include <cuda_runtime.h>
#include <math.h>

namespace {
constexpr int B = 8, S = 4096, E = 1024, H = 8, W = 128, D = 128;
constexpr int NWIN = S / W;          // 32
constexpr int TPAD = 132;            // padded row stride (floats) for transposed smem tiles
constexpr float SCALE = 0.08838834764831845f;  // D^-0.5
}

// Scratch (device globals — no runtime allocation allowed)
__device__ float g_q[(size_t)B * H * S * D];
__device__ float g_k[(size_t)B * H * S * D];
__device__ float g_v[(size_t)B * H * S * D];
__device__ float g_att[(size_t)B * S * E];

// ---------------------------------------------------------------------------
// Tile loaders: 128x128 fp32 tile, 256 threads.
// Coalesced float4 gmem reads (one warp = one 512B row), scatter into smem.
// ---------------------------------------------------------------------------

// Transposed: smT[col][row], row stride TPAD. Optional scale folded in.
__device__ __forceinline__ void load_tile_T(const float* __restrict__ g, int row_stride,
                                            float* __restrict__ smT, int t, float scale)
{
#pragma unroll
    for (int v = 0; v < 16; v++) {
        int lin = t + v * 256;          // quad index 0..4095
        int row = lin >> 5;             // 0..127
        int qc  = (lin & 31) << 2;      // column base 0..124
        float4 f = *reinterpret_cast<const float4*>(g + (long)row * row_stride + qc);
        smT[(qc + 0) * TPAD + row] = f.x * scale;
        smT[(qc + 1) * TPAD + row] = f.y * scale;
        smT[(qc + 2) * TPAD + row] = f.z * scale;
        smT[(qc + 3) * TPAD + row] = f.w * scale;
    }
}

// Natural: sm[row][col], row stride 128 (float4-aligned).
__device__ __forceinline__ void load_tile_N(const float* __restrict__ g, int row_stride,
                                            float* __restrict__ sm, int t)
{
#pragma unroll
    for (int v = 0; v < 16; v++) {
        int lin = t + v * 256;
        int row = lin >> 5;
        int qc  = (lin & 31) << 2;
        *reinterpret_cast<float4*>(sm + row * 128 + qc) =
            *reinterpret_cast<const float4*>(g + (long)row * row_stride + qc);
    }
}

// ---------------------------------------------------------------------------
// Kernel 1: per-head projection. out[b,h,s,o] = sum_d x[b,s,h*D+d] * Wt[o,d]
// grid (S/128, H, B), 256 threads, 8x8 register tile per thread.
// ---------------------------------------------------------------------------
__global__ void __launch_bounds__(256)
proj_kernel(const float* __restrict__ x, const float* __restrict__ Wt,
            float* __restrict__ out)
{
    extern __shared__ float sm[];
    float* xsT = sm;                 // [128][TPAD]  xsT[d][row]
    float* WsT = sm + 128 * TPAD;    // [128][TPAD]  WsT[d][o]

    const int t  = threadIdx.x;
    const int st = blockIdx.x, h = blockIdx.y, b = blockIdx.z;
    const int s0 = st * 128;

    load_tile_T(x + ((long)(b * S + s0)) * E + h * D, E, xsT, t, 1.0f);
    load_tile_T(Wt, D, WsT, t, 1.0f);
    __syncthreads();

    const int r0 = (t >> 4) << 3;
    const int c0 = (t & 15) << 3;
    float acc[8][8] = {};

#pragma unroll 4
    for (int kk = 0; kk < 128; kk++) {
        float4 a0 = *reinterpret_cast<float4*>(&xsT[kk * TPAD + r0]);
        float4 a1 = *reinterpret_cast<float4*>(&xsT[kk * TPAD + r0 + 4]);
        float4 b0 = *reinterpret_cast<float4*>(&WsT[kk * TPAD + c0]);
        float4 b1 = *reinterpret_cast<float4*>(&WsT[kk * TPAD + c0 + 4]);
        float a[8] = {a0.x, a0.y, a0.z, a0.w, a1.x, a1.y, a1.z, a1.w};
        float bb[8] = {b0.x, b0.y, b0.z, b0.w, b1.x, b1.y, b1.z, b1.w};
#pragma unroll
        for (int i = 0; i < 8; i++)
#pragma unroll
            for (int j = 0; j < 8; j++)
                acc[i][j] = fmaf(a[i], bb[j], acc[i][j]);
    }

    long ob = ((long)(b * H + h) * S + s0 + r0) * D + c0;
#pragma unroll
    for (int i = 0; i < 8; i++) {
        *reinterpret_cast<float4*>(&out[ob + (long)i * D]) =
            make_float4(acc[i][0], acc[i][1], acc[i][2], acc[i][3]);
        *reinterpret_cast<float4*>(&out[ob + (long)i * D + 4]) =
            make_float4(acc[i][4], acc[i][5], acc[i][6], acc[i][7]);
    }
}

// ---------------------------------------------------------------------------
// Kernel 2: sliding-window attention. One block per (window, head, batch).
// Flash-style over the 3 neighbor windows; skipped out-of-range window ==
// reference's finfo.min mask (exp underflows to exactly 0).
// Output layout [b, s, h*D+d] so fc_out reads contiguously.
// ---------------------------------------------------------------------------
__global__ void __launch_bounds__(256)
attn_kernel(const float* __restrict__ gq, const float* __restrict__ gk,
            const float* __restrict__ gv, float* __restrict__ gout)
{
    extern __shared__ float sm[];
    float* qsT = sm;                               // [128][TPAD]  q^T (pre-scaled)
    float* ksT = sm + 128 * TPAD;                  // [128][TPAD]  k^T, reused as p^T
    float* vs  = sm + 2 * 128 * TPAD;              // [128][128]   v natural

    const int t  = threadIdx.x;
    const int wi = blockIdx.x, h = blockIdx.y, b = blockIdx.z;
    const long base = (long)(b * H + h) * S * D;

    load_tile_T(gq + base + (long)wi * W * D, D, qsT, t, SCALE);

    const int r0 = (t >> 4) << 3;   // query rows owned
    const int c0 = (t & 15) << 3;   // key cols (phase 1) / d cols (phase 2)

    float m[8], l[8], acc[8][8] = {};
#pragma unroll
    for (int i = 0; i < 8; i++) { m[i] = -1e30f; l[i] = 0.0f; }

    for (int c = 0; c < 3; c++) {
        const int j = wi - 1 + c;
        if (j < 0 || j >= NWIN) continue;     // uniform across block

        __syncthreads();  // previous PV done reading ksT/vs; qsT load visible
        load_tile_T(gk + base + (long)j * W * D, D, ksT, t, 1.0f);
        load_tile_N(gv + base + (long)j * W * D, D, vs, t);
        __syncthreads();

        // --- S = q k^T (scaled) ---
        float s[8][8] = {};
#pragma unroll 4
        for (int kk = 0; kk < 128; kk++) {
            float4 a0 = *reinterpret_cast<float4*>(&qsT[kk * TPAD + r0]);
            float4 a1 = *reinterpret_cast<float4*>(&qsT[kk * TPAD + r0 + 4]);
            float4 b0 = *reinterpret_cast<float4*>(&ksT[kk * TPAD + c0]);
            float4 b1 = *reinterpret_cast<float4*>(&ksT[kk * TPAD + c0 + 4]);
            float a[8] = {a0.x, a0.y, a0.z, a0.w, a1.x, a1.y, a1.z, a1.w};
            float bb[8] = {b0.x, b0.y, b0.z, b0.w, b1.x, b1.y, b1.z, b1.w};
#pragma unroll
            for (int i = 0; i < 8; i++)
#pragma unroll
                for (int jj = 0; jj < 8; jj++)
                    s[i][jj] = fmaf(a[i], bb[jj], s[i][jj]);
        }

        // --- online softmax (row stats across the 16-lane tx group) ---
        float mn[8], alpha[8];
#pragma unroll
        for (int i = 0; i < 8; i++) {
            float cm = s[i][0];
#pragma unroll
            for (int jj = 1; jj < 8; jj++) cm = fmaxf(cm, s[i][jj]);
#pragma unroll
            for (int off = 8; off >= 1; off >>= 1)
                cm = fmaxf(cm, __shfl_xor_sync(0xffffffffu, cm, off));
            mn[i] = fmaxf(m[i], cm);
            alpha[i] = __expf(m[i] - mn[i]);
            float rs = 0.0f;
#pragma unroll
            for (int jj = 0; jj < 8; jj++) {
                s[i][jj] = __expf(s[i][jj] - mn[i]);
                rs += s[i][jj];
            }
#pragma unroll
            for (int off = 8; off >= 1; off >>= 1)
                rs += __shfl_xor_sync(0xffffffffu, rs, off);
            l[i] = l[i] * alpha[i] + rs;
            m[i] = mn[i];
        }
#pragma unroll
        for (int i = 0; i < 8; i++)
#pragma unroll
            for (int jj = 0; jj < 8; jj++) acc[i][jj] *= alpha[i];

        // --- write p^T into ksT (all reads of k finished) ---
        __syncthreads();
#pragma unroll
        for (int jj = 0; jj < 8; jj++) {
            *reinterpret_cast<float4*>(&ksT[(c0 + jj) * TPAD + r0]) =
                make_float4(s[0][jj], s[1][jj], s[2][jj], s[3][jj]);
            *reinterpret_cast<float4*>(&ksT[(c0 + jj) * TPAD + r0 + 4]) =
                make_float4(s[4][jj], s[5][jj], s[6][jj], s[7][jj]);
        }
        __syncthreads();

        // --- acc += p v ---
#pragma unroll 4
        for (int kk = 0; kk < 128; kk++) {
            float4 a0 = *reinterpret_cast<float4*>(&ksT[kk * TPAD + r0]);
            float4 a1 = *reinterpret_cast<float4*>(&ksT[kk * TPAD + r0 + 4]);
            float4 b0 = *reinterpret_cast<float4*>(&vs[kk * 128 + c0]);
            float4 b1 = *reinterpret_cast<float4*>(&vs[kk * 128 + c0 + 4]);
            float a[8] = {a0.x, a0.y, a0.z, a0.w, a1.x, a1.y, a1.z, a1.w};
            float bb[8] = {b0.x, b0.y, b0.z, b0.w, b1.x, b1.y, b1.z, b1.w};
#pragma unroll
            for (int i = 0; i < 8; i++)
#pragma unroll
                for (int jj = 0; jj < 8; jj++)
                    acc[i][jj] = fmaf(a[i], bb[jj], acc[i][jj]);
        }
    }

    // epilogue: normalize, store to [b, s, h*D + d]
#pragma unroll
    for (int i = 0; i < 8; i++) {
        float inv = 1.0f / l[i];
        long ob = ((long)(b * S + wi * W + r0 + i)) * E + h * D + c0;
        *reinterpret_cast<float4*>(&gout[ob]) =
            make_float4(acc[i][0] * inv, acc[i][1] * inv, acc[i][2] * inv, acc[i][3] * inv);
        *reinterpret_cast<float4*>(&gout[ob + 4]) =
            make_float4(acc[i][4] * inv, acc[i][5] * inv, acc[i][6] * inv, acc[i][7] * inv);
    }
}

// ---------------------------------------------------------------------------
// Kernel 3: fc_out. y[m,o] = sum_e att[m,e]*Wo[o,e] + bo[o]
// M = B*S = 32768, N = K = 1024. grid (N/128, M/128), 128x128 tile, KC=64.
// ---------------------------------------------------------------------------
__global__ void __launch_bounds__(256)
fc_kernel(const float* __restrict__ att, const float* __restrict__ Wo,
          const float* __restrict__ bo, float* __restrict__ y)
{
    extern __shared__ float sm[];
    float* aT = sm;               // [64][TPAD]  a^T chunk
    float* bT = sm + 64 * TPAD;   // [64][TPAD]  Wo^T chunk

    const int t  = threadIdx.x;
    const int n0 = blockIdx.x * 128;
    const int m0 = blockIdx.y * 128;
    const int r0 = (t >> 4) << 3;
    const int c0 = (t & 15) << 3;

    float acc[8][8] = {};

    for (int e0 = 0; e0 < E; e0 += 64) {
        __syncthreads();
#pragma unroll
        for (int v = 0; v < 8; v++) {
            int lin = t + v * 256;       // quad index 0..2047
            int row = lin >> 4;          // 0..127
            int qc  = (lin & 15) << 2;   // 0..60
            float4 f = *reinterpret_cast<const float4*>(att + (long)(m0 + row) * E + e0 + qc);
            aT[(qc + 0) * TPAD + row] = f.x;
            aT[(qc + 1) * TPAD + row] = f.y;
            aT[(qc + 2) * TPAD + row] = f.z;
            aT[(qc + 3) * TPAD + row] = f.w;
            float4 g = *reinterpret_cast<const float4*>(Wo + (long)(n0 + row) * E + e0 + qc);
            bT[(qc + 0) * TPAD + row] = g.x;
            bT[(qc + 1) * TPAD + row] = g.y;
            bT[(qc + 2) * TPAD + row] = g.z;
            bT[(qc + 3) * TPAD + row] = g.w;
        }
        __syncthreads();

#pragma unroll 4
        for (int kk = 0; kk < 64; kk++) {
            float4 a0 = *reinterpret_cast<float4*>(&aT[kk * TPAD + r0]);
            float4 a1 = *reinterpret_cast<float4*>(&aT[kk * TPAD + r0 + 4]);
            float4 b0 = *reinterpret_cast<float4*>(&bT[kk * TPAD + c0]);
            float4 b1 = *reinterpret_cast<float4*>(&bT[kk * TPAD + c0 + 4]);
            float a[8] = {a0.x, a0.y, a0.z, a0.w, a1.x, a1.y, a1.z, a1.w};
            float bb[8] = {b0.x, b0.y, b0.z, b0.w, b1.x, b1.y, b1.z, b1.w};
#pragma unroll
            for (int i = 0; i < 8; i++)
#pragma unroll
                for (int jj = 0; jj < 8; jj++)
                    acc[i][jj] = fmaf(a[i], bb[jj], acc[i][jj]);
        }
    }

    float bias[8];
#pragma unroll
    for (int jj = 0; jj < 8; jj++) bias[jj] = bo[n0 + c0 + jj];

#pragma unroll
    for (int i = 0; i < 8; i++) {
        long ob = (long)(m0 + r0 + i) * E + n0 + c0;
        *reinterpret_cast<float4*>(&y[ob]) =
            make_float4(acc[i][0] + bias[0], acc[i][1] + bias[1],
                        acc[i][2] + bias[2], acc[i][3] + bias[3]);
        *reinterpret_cast<float4*>(&y[ob + 4]) =
            make_float4(acc[i][4] + bias[4], acc[i][5] + bias[5],
                        acc[i][6] + bias[6], acc[i][7] + bias[7]);
    }
}

// ---------------------------------------------------------------------------
// Launcher
// ---------------------------------------------------------------------------
extern "C" void kernel_launch(void* const* d_in, const int* in_sizes, int n_in,
                              void* d_out, int out_size)
{
    const float* values = (const float*)d_in[0];
    const float* keys   = (const float*)d_in[1];
    const float* query  = (const float*)d_in[2];
    const float* Wv     = (const float*)d_in[3];
    const float* Wk     = (const float*)d_in[4];
    const float* Wq     = (const float*)d_in[5];
    const float* Wo     = (const float*)d_in[6];
    const float* bo     = (const float*)d_in[7];
    float* out = (float*)d_out;

    float *q, *k, *v, *att;
    cudaGetSymbolAddress((void**)&q, g_q);
    cudaGetSymbolAddress((void**)&k, g_k);
    cudaGetSymbolAddress((void**)&v, g_v);
    cudaGetSymbolAddress((void**)&att, g_att);

    const size_t proj_smem = (size_t)2 * 128 * TPAD * sizeof(float);              // 135168
    const size_t attn_smem = ((size_t)2 * 128 * TPAD + 128 * 128) * sizeof(float); // 200704
    const size_t fc_smem   = (size_t)2 * 64 * TPAD * sizeof(float);               // 67584

    cudaFuncSetAttribute(proj_kernel, cudaFuncAttributeMaxDynamicSharedMemorySize, (int)proj_smem);
    cudaFuncSetAttribute(attn_kernel, cudaFuncAttributeMaxDynamicSharedMemorySize, (int)attn_smem);
    cudaFuncSetAttribute(fc_kernel,   cudaFuncAttributeMaxDynamicSharedMemorySize, (int)fc_smem);

    dim3 pg(S / 128, H, B);
    proj_kernel<<<pg, 256, proj_smem>>>(query,  Wq, q);
    proj_kernel<<<pg, 256, proj_smem>>>(keys,   Wk, k);
    proj_kernel<<<pg, 256, proj_smem>>>(values, Wv, v);

    attn_kernel<<<dim3(NWIN, H, B), 256, attn_smem>>>(q, k, v, att);

    fc_kernel<<<dim3(E / 128, (B * S) / 128), 256, fc_smem>>>(att, Wo, bo, out);
}